// round 14
// baseline (speedup 1.0000x reference)
#include <cuda_runtime.h>

// ============================================================================
// FINAL KERNEL — HilbertSimulator (4-qubit VQC forward, BATCH=2^21)
//
// Algebraic collapse (derived R0, verified against reference structure):
//   The circuit is RY-data-encoding -> RY-weights -> CNOT ring -> probs @ Z.
//   RYs on a real product state compose by angle addition; the CNOT ring is
//   GF(2)-linear, so probs@Z factorizes per qubit:
//     theta_i = x[b,i] + w[i],  c_i = cos(2*theta_i)
//     out[b]  = { c1*c2*c3, c0*c1, c0*c1*c2, c0*c1*c2*c3 }
//
// Optimization series conclusion (13 rounds):
//   15.0us (software cosf, issue-bound) -> 10.7us (MUFU.COS, latency floor).
//   The ~10.7us floor = ~2.7us launch/ramp + ~8us streaming bound by
//   exposed L2/DRAM round-trip latency; invariant to work-per-thread (1-8),
//   MLP shape, LDG.128/LDG.256/cp.async, L2 evict hints, prefetch, and CTA
//   geometry — all pipes <=40% at the floor. Flat 1-float4-per-thread is
//   the measured best (10.688us) and the simplest.
// ============================================================================

__device__ __forceinline__ float4 proc(float4 xv, float w0, float w1,
                                       float w2, float w3)
{
    float c0 = __cosf(fmaf(2.0f, xv.x, w0));
    float c1 = __cosf(fmaf(2.0f, xv.y, w1));
    float c2 = __cosf(fmaf(2.0f, xv.z, w2));
    float c3 = __cosf(fmaf(2.0f, xv.w, w3));
    float t01  = c0 * c1;
    float t012 = t01 * c2;
    float4 o;
    o.x = c1 * c2 * c3;
    o.y = t01;
    o.z = t012;
    o.w = t012 * c3;
    return o;
}

__global__ void __launch_bounds__(256)
hilbert_flat(const float4* __restrict__ x4,
             const float* __restrict__ w,
             float4* __restrict__ out4, int n)
{
    int i = blockIdx.x * blockDim.x + threadIdx.x;
    if (i >= n) return;
    float w0 = 2.0f * w[0], w1 = 2.0f * w[1];
    float w2 = 2.0f * w[2], w3 = 2.0f * w[3];
    out4[i] = proc(x4[i], w0, w1, w2, w3);
}

extern "C" void kernel_launch(void* const* d_in, const int* in_sizes, int n_in,
                              void* d_out, int out_size)
{
    const float* x = (const float*)d_in[0];
    const float* w = (const float*)d_in[1];
    int nx = in_sizes[0];
    if (n_in >= 2 && in_sizes[0] < in_sizes[1]) {
        x = (const float*)d_in[1];
        w = (const float*)d_in[0];
        nx = in_sizes[1];
    }

    int n = nx / 4;  // float4 count (= batch)
    int threads = 256;
    int blocks = (n + threads - 1) / threads;   // 8192 for BATCH=2^21

    hilbert_flat<<<blocks, threads>>>(
        (const float4*)x, w, (float4*)d_out, n);
}

// round 15
// speedup vs baseline: 1.1976x; 1.1976x over previous
#include <cuda_runtime.h>

// ============================================================================
// FINAL KERNEL — HilbertSimulator (4-qubit VQC forward, BATCH=2^21)
//
// Algebraic collapse (derived R0, verified against reference structure):
//   The circuit is RY-data-encoding -> RY-weights -> CNOT ring -> probs @ Z.
//   RYs on a real product state compose by angle addition; the CNOT ring is
//   GF(2)-linear, so probs@Z factorizes per qubit:
//     theta_i = x[b,i] + w[i],  c_i = cos(2*theta_i)
//     out[b]  = { c1*c2*c3, c0*c1, c0*c1*c2, c0*c1*c2*c3 }
//
// Optimization series conclusion (14 rounds):
//   15.0us (software cosf, issue-bound) -> 10.7us (MUFU.COS, latency floor).
//   Floor = launch/ramp overhead + streaming phase bound by exposed L2/DRAM
//   round-trip latency. Invariant to work-per-thread (1-8), MLP shape,
//   LDG.128/LDG.256/cp.async, L2 evict hints, prefetch, CTA geometry.
//   Identical-source benches span 10.69-12.80us (DVFS/clock residency env
//   noise, confirmed by whole-chip HBM-rate shift in ncu) — all remaining
//   variance is environmental, not kernel-side. Flat 1-float4-per-thread is
//   the measured best and simplest; locked in.
// ============================================================================

__device__ __forceinline__ float4 proc(float4 xv, float w0, float w1,
                                       float w2, float w3)
{
    float c0 = __cosf(fmaf(2.0f, xv.x, w0));
    float c1 = __cosf(fmaf(2.0f, xv.y, w1));
    float c2 = __cosf(fmaf(2.0f, xv.z, w2));
    float c3 = __cosf(fmaf(2.0f, xv.w, w3));
    float t01  = c0 * c1;
    float t012 = t01 * c2;
    float4 o;
    o.x = c1 * c2 * c3;
    o.y = t01;
    o.z = t012;
    o.w = t012 * c3;
    return o;
}

__global__ void __launch_bounds__(256)
hilbert_flat(const float4* __restrict__ x4,
             const float* __restrict__ w,
             float4* __restrict__ out4, int n)
{
    int i = blockIdx.x * blockDim.x + threadIdx.x;
    if (i >= n) return;
    float w0 = 2.0f * w[0], w1 = 2.0f * w[1];
    float w2 = 2.0f * w[2], w3 = 2.0f * w[3];
    out4[i] = proc(x4[i], w0, w1, w2, w3);
}

extern "C" void kernel_launch(void* const* d_in, const int* in_sizes, int n_in,
                              void* d_out, int out_size)
{
    const float* x = (const float*)d_in[0];
    const float* w = (const float*)d_in[1];
    int nx = in_sizes[0];
    if (n_in >= 2 && in_sizes[0] < in_sizes[1]) {
        x = (const float*)d_in[1];
        w = (const float*)d_in[0];
        nx = in_sizes[1];
    }

    int n = nx / 4;  // float4 count (= batch)
    int threads = 256;
    int blocks = (n + threads - 1) / threads;   // 8192 for BATCH=2^21

    hilbert_flat<<<blocks, threads>>>(
        (const float4*)x, w, (float4*)d_out, n);
}